// round 1
// baseline (speedup 1.0000x reference)
#include <cuda_runtime.h>

// Problem constants: B=4, L=2048, H=8, D=64, M=256, T=128 (chunk), NB=16 chunks/head
#define NRMc   0.35355339059327373f   // 64^-0.25 = 1/sqrt(8)
#define RATIOc 0.0625f                // 1/sqrt(256)
#define KEPSc  1e-4f

// Scratch (static device globals; no allocation at launch time)
__device__ float g_qp[16777216];   // [65536 rows][256]  query features
__device__ float g_kp[16777216];   // [65536 rows][256]  key dash -> key features (in place)
__device__ float g_kv[8388608];    // [32*16][256][64]   block KV sums -> exclusive prefix
__device__ float g_s[131072];      // [32*16][256]       block k-sums -> exclusive prefix
__device__ float g_kmax[32];       // per (b,h) max of key data_dash

__device__ __forceinline__ void atomicMaxFloat(float* addr, float v) {
    if (v >= 0.f) atomicMax((int*)addr, __float_as_int(v));
    else          atomicMin((unsigned int*)addr, __float_as_uint(v));
}

__global__ void k_init() {
    if (threadIdx.x < 32) g_kmax[threadIdx.x] = __int_as_float(0xff800000); // -inf
}

// ---------------------------------------------------------------------------
// Feature GEMM: rows = (b,l,h) flattened (65536), dash = (NRM*x) @ proj^T.
// 64 rows x 256 cols per block; thread owns column m, 64 row-accumulators.
// Queries: full feature (row-stab local). Keys: write dash-diag, atomicMax dash.
// ---------------------------------------------------------------------------
__global__ __launch_bounds__(256) void k_feat(const float* __restrict__ x,
                                              const float* __restrict__ proj,
                                              int is_query) {
    extern __shared__ float sm[];
    float* q_s   = sm;           // [64][64], pre-scaled by NRM
    float* projT = sm + 4096;    // [64][257] (padded, conflict-free)
    float* dash  = projT;        // alias: reused after GEMM
    __shared__ float rmax_s[64];
    __shared__ float diag_s[64];

    int tid = threadIdx.x;
    int n0  = blockIdx.x * 64;
    float* outp = is_query ? g_qp : g_kp;

    for (int idx = tid; idx < 4096; idx += 256) {
        int r = idx >> 6, d = idx & 63;
        q_s[idx] = NRMc * x[(size_t)(n0 + r) * 64 + d];
    }
    for (int idx = tid; idx < 16384; idx += 256) {
        int m = idx >> 6, d = idx & 63;
        projT[d * 257 + m] = proj[idx];
    }
    __syncthreads();

    if (tid < 64) {  // diag = 0.5*||NRM*x||^2
        const float4* qr = (const float4*)&q_s[tid * 64];
        float ssum = 0.f;
        #pragma unroll
        for (int i = 0; i < 16; i++) {
            float4 t = qr[i];
            ssum += t.x*t.x + t.y*t.y + t.z*t.z + t.w*t.w;
        }
        diag_s[tid] = 0.5f * ssum;
    }

    float acc[64];
    #pragma unroll
    for (int r = 0; r < 64; r++) acc[r] = 0.f;
    int m = tid;
    #pragma unroll 1
    for (int d4 = 0; d4 < 16; d4++) {
        float p0 = projT[(d4*4+0)*257 + m];
        float p1 = projT[(d4*4+1)*257 + m];
        float p2 = projT[(d4*4+2)*257 + m];
        float p3 = projT[(d4*4+3)*257 + m];
        #pragma unroll
        for (int r = 0; r < 64; r++) {
            float4 q4 = *(const float4*)&q_s[r*64 + d4*4];
            acc[r] += q4.x*p0 + q4.y*p1 + q4.z*p2 + q4.w*p3;
        }
    }
    __syncthreads();   // GEMM reads of projT done; safe to overwrite with dash

    #pragma unroll 1
    for (int r = 0; r < 64; r++) dash[r*257 + m] = acc[r];
    __syncthreads();

    if (tid < 64) {
        float mx = __int_as_float(0xff800000);
        #pragma unroll 1
        for (int mm = 0; mm < 256; mm++) mx = fmaxf(mx, dash[tid*257 + mm]);
        rmax_s[tid] = mx;
        if (!is_query) {
            int n = n0 + tid;   // h = n%8, b = n/16384
            atomicMaxFloat(&g_kmax[((n >> 14) << 3) | (n & 7)], mx);
        }
    }
    __syncthreads();

    #pragma unroll 1
    for (int r = 0; r < 64; r++) {
        float val = acc[r] - diag_s[r];
        if (is_query) val = RATIOc * (expf(val - rmax_s[r]) + KEPSc);
        outp[(size_t)(n0 + r) * 256 + m] = val;
    }
}

// kp[i] = ratio*(exp(kd - kmax[b,h]) + eps), in place, float4 grid
__global__ void k_kfinish() {
    size_t i = ((size_t)blockIdx.x * 256 + threadIdx.x) * 4;
    int n = (int)(i >> 8);
    float st = g_kmax[((n >> 14) << 3) | (n & 7)];
    float4 t = *(float4*)&g_kp[i];
    t.x = RATIOc * (expf(t.x - st) + KEPSc);
    t.y = RATIOc * (expf(t.y - st) + KEPSc);
    t.z = RATIOc * (expf(t.z - st) + KEPSc);
    t.w = RATIOc * (expf(t.w - st) + KEPSc);
    *(float4*)&g_kp[i] = t;
}

// ---------------------------------------------------------------------------
// Per-block KV = Kp^T @ V (256x64) and S = col-sums of Kp. grid = 512.
// ---------------------------------------------------------------------------
__global__ __launch_bounds__(256) void k_kvblk(const float* __restrict__ v) {
    __shared__ float v_s[8192];  // [128][64]
    int bh = blockIdx.x >> 4, j = blockIdx.x & 15;
    int b = bh >> 3, h = bh & 7;
    int tid = threadIdx.x;
    size_t rowbase = (size_t)(b * 2048 + j * 128) * 8 + h;

    for (int idx = tid; idx < 8192; idx += 256) {
        int u = idx >> 6, d = idx & 63;
        v_s[idx] = v[(rowbase + (size_t)u * 8) * 64 + d];
    }
    __syncthreads();

    float acc[64];
    #pragma unroll
    for (int d = 0; d < 64; d++) acc[d] = 0.f;
    float ssum = 0.f;
    int m = tid;
    #pragma unroll 1
    for (int u = 0; u < 128; u++) {
        float kv = g_kp[(rowbase + (size_t)u * 8) * 256 + m];
        ssum += kv;
        #pragma unroll
        for (int d4 = 0; d4 < 16; d4++) {
            float4 vv = *(float4*)&v_s[u*64 + d4*4];
            acc[d4*4+0] += kv * vv.x;
            acc[d4*4+1] += kv * vv.y;
            acc[d4*4+2] += kv * vv.z;
            acc[d4*4+3] += kv * vv.w;
        }
    }
    float* o = &g_kv[(size_t)blockIdx.x * 16384 + m * 64];
    #pragma unroll
    for (int d4 = 0; d4 < 16; d4++)
        *(float4*)&o[d4*4] = make_float4(acc[d4*4], acc[d4*4+1], acc[d4*4+2], acc[d4*4+3]);
    g_s[blockIdx.x * 256 + m] = ssum;
}

// Exclusive prefix over the 16 chunks of each head, in place. grid = 32*4.
__global__ void k_scan() {
    int bh = blockIdx.x >> 2, c = blockIdx.x & 3;
    int d0 = c * 16;
    int m = threadIdx.x;
    float run[16];
    #pragma unroll
    for (int k = 0; k < 16; k++) run[k] = 0.f;
    for (int j = 0; j < 16; j++) {
        float* p = &g_kv[((size_t)(bh*16 + j) * 256 + m) * 64 + d0];
        #pragma unroll
        for (int k4 = 0; k4 < 4; k4++) {
            float4 t = *(float4*)&p[k4*4];
            *(float4*)&p[k4*4] = make_float4(run[k4*4], run[k4*4+1], run[k4*4+2], run[k4*4+3]);
            run[k4*4] += t.x; run[k4*4+1] += t.y; run[k4*4+2] += t.z; run[k4*4+3] += t.w;
        }
    }
    if (c == 0) {
        float rs = 0.f;
        for (int j = 0; j < 16; j++) {
            size_t idx = (size_t)(bh*16 + j) * 256 + m;
            float t = g_s[idx]; g_s[idx] = rs; rs += t;
        }
    }
}

// ---------------------------------------------------------------------------
// Main attention block. grid = 512 (bh, j). 256 threads = 16x16 grid.
// Thread (tx,ty): A microtile rows t0..t0+7 x cols u0..u0+7,
//                 num microtile rows t0..t0+7 x d cols d0..d0+3.
// ---------------------------------------------------------------------------
__global__ __launch_bounds__(256, 1) void k_attn(const float* __restrict__ v,
                                                 float* __restrict__ out) {
    extern __shared__ float sm[];
    float* qpT  = sm;                  // [64][132]
    float* kpT  = sm + 8448;           // [64][132]
    float* Ps   = sm + 16896;          // [64][64]
    float* Ss   = sm + 20992;          // [64]
    float* Asm  = sm;                  // alias over qpT+kpT: [128][132]
    float* den1 = sm + 21056;          // [128]
    float* den2 = sm + 21184;          // [128]
    float* v_s  = sm + 21312;          // [128][64]

    int tid = threadIdx.x;
    int tx = tid & 15, ty = tid >> 4;
    int t0 = ty * 8, u0 = tx * 8, d0 = tx * 4;
    int bh = blockIdx.x >> 4, j = blockIdx.x & 15;
    int b = bh >> 3, h = bh & 7;
    size_t rowbase = (size_t)(b * 2048 + j * 128) * 8 + h;

    for (int idx = tid; idx < 8192; idx += 256) {
        int u = idx >> 6, d = idx & 63;
        v_s[idx] = v[(rowbase + (size_t)u * 8) * 64 + d];
    }

    float A[8][8];
    float NP[8][4];
    #pragma unroll
    for (int i = 0; i < 8; i++) {
        #pragma unroll
        for (int jj = 0; jj < 8; jj++) A[i][jj] = 0.f;
        #pragma unroll
        for (int jj = 0; jj < 4; jj++) NP[i][jj] = 0.f;
    }
    float denq = 0.f;

    #pragma unroll 1
    for (int mc = 0; mc < 4; mc++) {
        __syncthreads();  // protect previous chunk (and v_s on first iter)
        for (int idx = tid; idx < 8192; idx += 256) {
            int t = idx >> 6, mm = idx & 63;
            size_t g = (rowbase + (size_t)t * 8) * 256 + mc * 64 + mm;
            qpT[mm*132 + t] = g_qp[g];
            kpT[mm*132 + t] = g_kp[g];
        }
        for (int idx = tid; idx < 4096; idx += 256)
            Ps[idx] = g_kv[(size_t)blockIdx.x * 16384 + mc * 4096 + idx];
        if (tid < 64) Ss[tid] = g_s[(size_t)blockIdx.x * 256 + mc * 64 + tid];
        __syncthreads();

        #pragma unroll 1
        for (int mm = 0; mm < 64; mm++) {
            float4 qa = *(float4*)&qpT[mm*132 + t0];
            float4 qb = *(float4*)&qpT[mm*132 + t0 + 4];
            float4 ka = *(float4*)&kpT[mm*132 + u0];
            float4 kb = *(float4*)&kpT[mm*132 + u0 + 4];
            float4 pv = *(float4*)&Ps[mm*64 + d0];
            float qv[8] = {qa.x,qa.y,qa.z,qa.w,qb.x,qb.y,qb.z,qb.w};
            float kv[8] = {ka.x,ka.y,ka.z,ka.w,kb.x,kb.y,kb.z,kb.w};
            #pragma unroll
            for (int i = 0; i < 8; i++) {
                #pragma unroll
                for (int jj = 0; jj < 8; jj++) A[i][jj] += qv[i] * kv[jj];
                NP[i][0] += qv[i] * pv.x;
                NP[i][1] += qv[i] * pv.y;
                NP[i][2] += qv[i] * pv.z;
                NP[i][3] += qv[i] * pv.w;
            }
        }
        // den partial: q . S_prev (threads 0..127 own one t each)
        if (tid < 128) {
            #pragma unroll 1
            for (int mm = 0; mm < 64; mm++) denq += qpT[mm*132 + tid] * Ss[mm];
        }
    }
    __syncthreads();   // all reads of qpT/kpT done; alias as Asm now

    #pragma unroll
    for (int i = 0; i < 8; i++) {
        *(float4*)&Asm[(t0+i)*132 + u0]     = make_float4(A[i][0],A[i][1],A[i][2],A[i][3]);
        *(float4*)&Asm[(t0+i)*132 + u0 + 4] = make_float4(A[i][4],A[i][5],A[i][6],A[i][7]);
    }
    if (tid < 128) den1[tid] = denq;
    __syncthreads();

    // Intra-block causal AV + row sums of masked A
    float dsum[8];
    #pragma unroll
    for (int i = 0; i < 8; i++) dsum[i] = 0.f;
    int ulim = t0 + 8;
    #pragma unroll 1
    for (int u = 0; u < ulim; u++) {
        float4 vv = *(float4*)&v_s[u*64 + d0];
        #pragma unroll
        for (int i = 0; i < 8; i++) {
            float a = Asm[(t0+i)*132 + u];
            a = (u <= t0 + i) ? a : 0.f;
            NP[i][0] += a * vv.x;
            NP[i][1] += a * vv.y;
            NP[i][2] += a * vv.z;
            NP[i][3] += a * vv.w;
            if (tx == 0) dsum[i] += a;
        }
    }
    if (tx == 0) {
        #pragma unroll
        for (int i = 0; i < 8; i++) den2[t0+i] = dsum[i];
    }
    __syncthreads();

    #pragma unroll
    for (int i = 0; i < 8; i++) {
        float den = den1[t0+i] + den2[t0+i];
        den += (fabsf(den) <= 1e-6f) ? 2e-6f : 0.f;
        float inv = 1.f / den;
        float4 o = make_float4(NP[i][0]*inv, NP[i][1]*inv, NP[i][2]*inv, NP[i][3]*inv);
        *(float4*)&out[(rowbase + (size_t)(t0+i) * 8) * 64 + d0] = o;
    }
}

extern "C" void kernel_launch(void* const* d_in, const int* in_sizes, int n_in,
                              void* d_out, int out_size) {
    const float* q    = (const float*)d_in[0];
    const float* k    = (const float*)d_in[1];
    const float* v    = (const float*)d_in[2];
    const float* proj = (const float*)d_in[3];
    float* out = (float*)d_out;
    (void)in_sizes; (void)n_in; (void)out_size;

    const int SMF = 82176;    // k_feat dynamic smem bytes
    const int SMA = 118016;   // k_attn dynamic smem bytes
    cudaFuncSetAttribute(k_feat, cudaFuncAttributeMaxDynamicSharedMemorySize, SMF);
    cudaFuncSetAttribute(k_attn, cudaFuncAttributeMaxDynamicSharedMemorySize, SMA);

    k_init<<<1, 32>>>();
    k_feat<<<1024, 256, SMF>>>(q, proj, 1);      // query features
    k_feat<<<1024, 256, SMF>>>(k, proj, 0);      // key dash + global max
    k_kfinish<<<16384, 256>>>();                 // key features
    k_kvblk<<<512, 256>>>(v);                    // per-chunk KV, S
    k_scan<<<128, 256>>>();                      // exclusive prefix over chunks
    k_attn<<<512, 256, SMA>>>(v, out);           // main attention
}

// round 4
// speedup vs baseline: 1.7316x; 1.7316x over previous
#include <cuda_runtime.h>

// B=4, L=2048, H=8, D=64, M=256, chunk T=128, 16 chunks/head
#define NRMc   0.35355339059327373f   // 64^-0.25
#define RATIOc 0.0625f                // 1/sqrt(256)
#define KEPSc  1e-4f

__device__ float g_qp[16777216];   // [65536][256] query features
__device__ float g_kp[16777216];   // [65536][256] key dash -> features (in place)
__device__ float g_kv[8388608];    // [512][256][64] block KV -> exclusive prefix
__device__ float g_s[131072];      // [512][256]    block k-sums -> exclusive prefix
__device__ float g_kmax[32];

__device__ __forceinline__ void atomicMaxFloat(float* addr, float v) {
    if (v >= 0.f) atomicMax((int*)addr, __float_as_int(v));
    else          atomicMin((unsigned int*)addr, __float_as_uint(v));
}

__global__ void k_init() {
    if (threadIdx.x < 32) g_kmax[threadIdx.x] = __int_as_float(0xff800000);
}

// ---------------- 3xTF32 MMA helpers (m16n8k8, row.col, fp32-accurate) -----
__device__ __forceinline__ void f2tf2(float f, unsigned& h, unsigned& l) {
    asm("cvt.rna.tf32.f32 %0, %1;" : "=r"(h) : "f"(f));
    float r = f - __uint_as_float(h);
    asm("cvt.rna.tf32.f32 %0, %1;" : "=r"(l) : "f"(r));
}
struct FA { unsigned h[4]; unsigned l[4]; };
struct FB { unsigned h[2]; unsigned l[2]; };

__device__ __forceinline__ void mma8(float c[4], const unsigned a[4], const unsigned b[2]) {
    asm volatile("mma.sync.aligned.m16n8k8.row.col.f32.tf32.tf32.f32 "
                 "{%0,%1,%2,%3},{%4,%5,%6,%7},{%8,%9},{%0,%1,%2,%3};"
                 : "+f"(c[0]), "+f"(c[1]), "+f"(c[2]), "+f"(c[3])
                 : "r"(a[0]), "r"(a[1]), "r"(a[2]), "r"(a[3]), "r"(b[0]), "r"(b[1]));
}
__device__ __forceinline__ void mma3(float c[4], const FA& a, const FB& b) {
    mma8(c, a.l, b.h);   // small terms first
    mma8(c, a.h, b.l);
    mma8(c, a.h, b.h);
}
// A[r][k] from row-major S[r][k] (pitch P)
__device__ __forceinline__ void lda(FA& a, const float* S, int P, int r, int k, int g, int t) {
    f2tf2(S[(r+g)*P + k + t],       a.h[0], a.l[0]);
    f2tf2(S[(r+g+8)*P + k + t],     a.h[1], a.l[1]);
    f2tf2(S[(r+g)*P + k + t + 4],   a.h[2], a.l[2]);
    f2tf2(S[(r+g+8)*P + k + t + 4], a.h[3], a.l[3]);
}
// A[r][k] from S stored [k][r] (pitch P)
__device__ __forceinline__ void lda_t(FA& a, const float* S, int P, int r, int k, int g, int t) {
    f2tf2(S[(k+t)*P + r + g],       a.h[0], a.l[0]);
    f2tf2(S[(k+t)*P + r + g + 8],   a.h[1], a.l[1]);
    f2tf2(S[(k+t+4)*P + r + g],     a.h[2], a.l[2]);
    f2tf2(S[(k+t+4)*P + r + g + 8], a.h[3], a.l[3]);
}
// B[k][n] from S stored row-major [n][k] (pitch P)
__device__ __forceinline__ void ldb_nk(FB& b, const float* S, int P, int n, int k, int g, int t) {
    f2tf2(S[(n+g)*P + k + t],     b.h[0], b.l[0]);
    f2tf2(S[(n+g)*P + k + t + 4], b.h[1], b.l[1]);
}
// B[k][n] from S stored row-major [k][n] (pitch P)
__device__ __forceinline__ void ldb_kn(FB& b, const float* S, int P, int k, int n, int g, int t) {
    f2tf2(S[(k+t)*P + n + g],     b.h[0], b.l[0]);
    f2tf2(S[(k+t+4)*P + n + g],   b.h[1], b.l[1]);
}

// ---------------------------------------------------------------------------
// Features: dash[64x256] = (NRM*X)[64x64] @ P^T, per block of 64 rows.
// ---------------------------------------------------------------------------
__global__ __launch_bounds__(256) void k_feat(const float* __restrict__ x,
                                              const float* __restrict__ proj,
                                              int is_query) {
    extern __shared__ float sm[];
    float* q_s    = sm;            // [64][68]
    float* proj_s = sm + 4352;     // [256][68]
    float* dash   = proj_s;        // alias after GEMM: [64][257]
    __shared__ float rmax_s[64];
    __shared__ float diag_s[64];

    int tid = threadIdx.x, lane = tid & 31, wid = tid >> 5;
    int g = lane >> 2, t = lane & 3;
    int wr = wid >> 2, wc = wid & 3;
    int n0 = blockIdx.x * 64;
    float* outp = is_query ? g_qp : g_kp;

    for (int idx = tid; idx < 1024; idx += 256) {
        int r = idx >> 4, d4 = idx & 15;
        float4 v = *(const float4*)&x[(size_t)(n0 + r) * 64 + d4 * 4];
        v.x *= NRMc; v.y *= NRMc; v.z *= NRMc; v.w *= NRMc;
        *(float4*)&q_s[r*68 + d4*4] = v;
    }
    for (int idx = tid; idx < 4096; idx += 256) {
        int m = idx >> 4, d4 = idx & 15;
        *(float4*)&proj_s[m*68 + d4*4] = *(const float4*)&proj[(size_t)m * 64 + d4 * 4];
    }
    __syncthreads();

    if (tid < 64) {
        float ssum = 0.f;
        #pragma unroll
        for (int i = 0; i < 16; i++) {
            float4 v = *(float4*)&q_s[tid*68 + i*4];
            ssum += v.x*v.x + v.y*v.y + v.z*v.z + v.w*v.w;
        }
        diag_s[tid] = 0.5f * ssum;
    }

    float C[2][8][4];
    #pragma unroll
    for (int mt = 0; mt < 2; mt++)
        #pragma unroll
        for (int nt = 0; nt < 8; nt++)
            #pragma unroll
            for (int i = 0; i < 4; i++) C[mt][nt][i] = 0.f;

    #pragma unroll 1
    for (int k0 = 0; k0 < 64; k0 += 8) {
        FA a[2]; FB b[8];
        #pragma unroll
        for (int mt = 0; mt < 2; mt++) lda(a[mt], q_s, 68, wr*32 + mt*16, k0, g, t);
        #pragma unroll
        for (int nt = 0; nt < 8; nt++) ldb_nk(b[nt], proj_s, 68, wc*64 + nt*8, k0, g, t);
        #pragma unroll
        for (int mt = 0; mt < 2; mt++)
            #pragma unroll
            for (int nt = 0; nt < 8; nt++) mma3(C[mt][nt], a[mt], b[nt]);
    }
    __syncthreads();

    #pragma unroll
    for (int mt = 0; mt < 2; mt++)
        #pragma unroll
        for (int nt = 0; nt < 8; nt++) {
            int r = wr*32 + mt*16 + g, c = wc*64 + nt*8 + 2*t;
            dash[r*257 + c]       = C[mt][nt][0];
            dash[r*257 + c + 1]   = C[mt][nt][1];
            dash[(r+8)*257 + c]   = C[mt][nt][2];
            dash[(r+8)*257 + c+1] = C[mt][nt][3];
        }
    __syncthreads();

    if (tid < 64) {
        float mx = __int_as_float(0xff800000);
        #pragma unroll 1
        for (int mm = 0; mm < 256; mm++) mx = fmaxf(mx, dash[tid*257 + mm]);
        rmax_s[tid] = mx;
        if (!is_query) {
            int n = n0 + tid;
            atomicMaxFloat(&g_kmax[((n >> 14) << 3) | (n & 7)], mx);
        }
    }
    __syncthreads();

    int m = tid;
    #pragma unroll 1
    for (int r = 0; r < 64; r++) {
        float val = dash[r*257 + m] - diag_s[r];
        if (is_query) val = RATIOc * (expf(val - rmax_s[r]) + KEPSc);
        outp[(size_t)(n0 + r) * 256 + m] = val;
    }
}

__global__ void k_kfinish() {
    size_t i = ((size_t)blockIdx.x * 256 + threadIdx.x) * 4;
    int n = (int)(i >> 8);
    float st = g_kmax[((n >> 14) << 3) | (n & 7)];
    float4 v = *(float4*)&g_kp[i];
    v.x = RATIOc * (expf(v.x - st) + KEPSc);
    v.y = RATIOc * (expf(v.y - st) + KEPSc);
    v.z = RATIOc * (expf(v.z - st) + KEPSc);
    v.w = RATIOc * (expf(v.w - st) + KEPSc);
    *(float4*)&g_kp[i] = v;
}

// ---------------------------------------------------------------------------
// Per-chunk KV[256x64] = Kp^T @ V, S[256] = colsum(Kp). grid = 512.
// ---------------------------------------------------------------------------
__global__ __launch_bounds__(256) void k_kvblk(const float* __restrict__ v) {
    extern __shared__ float sm[];
    float* kp_s = sm;            // [32][260]
    float* v_s  = sm + 8320;     // [32][68]

    int tid = threadIdx.x, lane = tid & 31, wid = tid >> 5;
    int g = lane >> 2, t = lane & 3;
    int wr = wid >> 1, wc = wid & 1;
    int bh = blockIdx.x >> 4, j = blockIdx.x & 15;
    int b = bh >> 3, h = bh & 7;
    size_t rowbase = (size_t)(b * 2048 + j * 128) * 8 + h;

    float C[4][4][4];
    #pragma unroll
    for (int mt = 0; mt < 4; mt++)
        #pragma unroll
        for (int nt = 0; nt < 4; nt++)
            #pragma unroll
            for (int i = 0; i < 4; i++) C[mt][nt][i] = 0.f;
    float ssum = 0.f;

    #pragma unroll 1
    for (int uc = 0; uc < 4; uc++) {
        __syncthreads();
        for (int idx = tid; idx < 2048; idx += 256) {
            int u = idx >> 6, m4 = idx & 63;
            *(float4*)&kp_s[u*260 + m4*4] =
                *(const float4*)&g_kp[(rowbase + (size_t)(uc*32 + u) * 8) * 256 + m4*4];
        }
        for (int idx = tid; idx < 512; idx += 256) {
            int u = idx >> 4, d4 = idx & 15;
            *(float4*)&v_s[u*68 + d4*4] =
                *(const float4*)&v[(rowbase + (size_t)(uc*32 + u) * 8) * 64 + d4*4];
        }
        __syncthreads();

        #pragma unroll
        for (int u = 0; u < 32; u++) ssum += kp_s[u*260 + tid];

        #pragma unroll
        for (int k0 = 0; k0 < 32; k0 += 8) {
            FA a[4]; FB bv[4];
            #pragma unroll
            for (int mt = 0; mt < 4; mt++) lda_t(a[mt], kp_s, 260, wr*64 + mt*16, k0, g, t);
            #pragma unroll
            for (int nt = 0; nt < 4; nt++) ldb_kn(bv[nt], v_s, 68, k0, wc*32 + nt*8, g, t);
            #pragma unroll
            for (int mt = 0; mt < 4; mt++)
                #pragma unroll
                for (int nt = 0; nt < 4; nt++) mma3(C[mt][nt], a[mt], bv[nt]);
        }
    }

    float* o = &g_kv[(size_t)blockIdx.x * 16384];
    #pragma unroll
    for (int mt = 0; mt < 4; mt++)
        #pragma unroll
        for (int nt = 0; nt < 4; nt++) {
            int m = wr*64 + mt*16 + g, d = wc*32 + nt*8 + 2*t;
            *(float2*)&o[m*64 + d]     = make_float2(C[mt][nt][0], C[mt][nt][1]);
            *(float2*)&o[(m+8)*64 + d] = make_float2(C[mt][nt][2], C[mt][nt][3]);
        }
    g_s[blockIdx.x * 256 + tid] = ssum;
}

// Exclusive prefix over 16 chunks/head, in place. grid = 128.
__global__ void k_scan() {
    int bh = blockIdx.x >> 2, c = blockIdx.x & 3;
    int d0 = c * 16;
    int m = threadIdx.x;
    float run[16];
    #pragma unroll
    for (int k = 0; k < 16; k++) run[k] = 0.f;
    for (int j = 0; j < 16; j++) {
        float* p = &g_kv[((size_t)(bh*16 + j) * 256 + m) * 64 + d0];
        #pragma unroll
        for (int k4 = 0; k4 < 4; k4++) {
            float4 v = *(float4*)&p[k4*4];
            *(float4*)&p[k4*4] = make_float4(run[k4*4], run[k4*4+1], run[k4*4+2], run[k4*4+3]);
            run[k4*4] += v.x; run[k4*4+1] += v.y; run[k4*4+2] += v.z; run[k4*4+3] += v.w;
        }
    }
    if (c == 0) {
        float rs = 0.f;
        for (int j = 0; j < 16; j++) {
            size_t idx = (size_t)(bh*16 + j) * 256 + m;
            float v = g_s[idx]; g_s[idx] = rs; rs += v;
        }
    }
}

// ---------------------------------------------------------------------------
// Attention block: A = Qp Kp^T (K=256, chunked 32), NP = Qp P_prev,
// AV = tril(A) V, den = Qp.S_prev + rowsum(tril A). grid = 512.
// ---------------------------------------------------------------------------
__global__ __launch_bounds__(256, 1) void k_attn(const float* __restrict__ v,
                                                 float* __restrict__ out) {
    extern __shared__ float sm[];
    float* qp_s = sm;           // [128][36]
    float* kp_s = sm + 4608;    // [128][36]
    float* ps_s = sm + 9216;    // [32][68]
    float* A_s  = sm;           // alias (phase 2): [128][132]
    float* v_s  = sm + 16896;   // [128][68]
    __shared__ float Ss_s[32];
    __shared__ float den1[128], den2[128];

    int tid = threadIdx.x, lane = tid & 31, wid = tid >> 5;
    int g = lane >> 2, t = lane & 3;
    int wr = wid >> 2, wc = wid & 3;
    int bh = blockIdx.x >> 4, j = blockIdx.x & 15;
    int b = bh >> 3, h = bh & 7;
    size_t rowbase = (size_t)(b * 2048 + j * 128) * 8 + h;

    float CA[4][4][4];
    float CN[4][2][4];
    #pragma unroll
    for (int mt = 0; mt < 4; mt++) {
        #pragma unroll
        for (int nt = 0; nt < 4; nt++)
            #pragma unroll
            for (int i = 0; i < 4; i++) CA[mt][nt][i] = 0.f;
        #pragma unroll
        for (int nt = 0; nt < 2; nt++)
            #pragma unroll
            for (int i = 0; i < 4; i++) CN[mt][nt][i] = 0.f;
    }
    float denq = 0.f;

    #pragma unroll 1
    for (int kc = 0; kc < 8; kc++) {
        __syncthreads();
        for (int idx = tid; idx < 1024; idx += 256) {
            int r = idx >> 3, k4 = idx & 7;
            *(float4*)&qp_s[r*36 + k4*4] =
                *(const float4*)&g_qp[(rowbase + (size_t)r * 8) * 256 + kc*32 + k4*4];
        }
        for (int idx = tid; idx < 1024; idx += 256) {
            int r = idx >> 3, k4 = idx & 7;
            *(float4*)&kp_s[r*36 + k4*4] =
                *(const float4*)&g_kp[(rowbase + (size_t)r * 8) * 256 + kc*32 + k4*4];
        }
        for (int idx = tid; idx < 512; idx += 256) {
            int kk = idx >> 4, d4 = idx & 15;
            *(float4*)&ps_s[kk*68 + d4*4] =
                *(const float4*)&g_kv[(size_t)blockIdx.x * 16384 + (kc*32 + kk)*64 + d4*4];
        }
        if (tid < 32) Ss_s[tid] = g_s[blockIdx.x * 256 + kc*32 + tid];
        if (kc == 0) {
            for (int idx = tid; idx < 2048; idx += 256) {
                int u = idx >> 4, d4 = idx & 15;
                *(float4*)&v_s[u*68 + d4*4] =
                    *(const float4*)&v[(rowbase + (size_t)u * 8) * 64 + d4*4];
            }
        }
        __syncthreads();

        #pragma unroll
        for (int k0 = 0; k0 < 32; k0 += 8) {
            FA a[4]; FB bA[4], bP[2];
            #pragma unroll
            for (int mt = 0; mt < 4; mt++) lda(a[mt], qp_s, 36, wr*64 + mt*16, k0, g, t);
            #pragma unroll
            for (int nt = 0; nt < 4; nt++) ldb_nk(bA[nt], kp_s, 36, wc*32 + nt*8, k0, g, t);
            #pragma unroll
            for (int nt = 0; nt < 2; nt++) ldb_kn(bP[nt], ps_s, 68, k0, wc*16 + nt*8, g, t);
            #pragma unroll
            for (int mt = 0; mt < 4; mt++) {
                #pragma unroll
                for (int nt = 0; nt < 4; nt++)
                    if (wc*32 + nt*8 <= wr*64 + mt*16 + 15)   // skip fully-masked tiles
                        mma3(CA[mt][nt], a[mt], bA[nt]);
                #pragma unroll
                for (int nt = 0; nt < 2; nt++) mma3(CN[mt][nt], a[mt], bP[nt]);
            }
        }
        if (tid < 128) {
            #pragma unroll
            for (int kk = 0; kk < 32; kk++) denq += qp_s[tid*36 + kk] * Ss_s[kk];
        }
    }
    __syncthreads();

    #pragma unroll
    for (int mt = 0; mt < 4; mt++)
        #pragma unroll
        for (int nt = 0; nt < 4; nt++) {
            int r = wr*64 + mt*16 + g, c = wc*32 + nt*8 + 2*t;
            A_s[r*132 + c]       = (c   <= r)   ? CA[mt][nt][0] : 0.f;
            A_s[r*132 + c + 1]   = (c+1 <= r)   ? CA[mt][nt][1] : 0.f;
            A_s[(r+8)*132 + c]   = (c   <= r+8) ? CA[mt][nt][2] : 0.f;
            A_s[(r+8)*132 + c+1] = (c+1 <= r+8) ? CA[mt][nt][3] : 0.f;
        }
    if (tid < 128) den1[tid] = denq;
    __syncthreads();

    if (tid < 128) {
        float rs = 0.f;
        #pragma unroll
        for (int u = 0; u < 128; u++) rs += A_s[tid*132 + u];
        den2[tid] = rs;
    }

    int kmax = wr*64 + 64;   // rows in this warp-row need u <= wr*64+63
    #pragma unroll 1
    for (int k0 = 0; k0 < kmax; k0 += 8) {
        FA a[4]; FB bV[2];
        #pragma unroll
        for (int mt = 0; mt < 4; mt++) lda(a[mt], A_s, 132, wr*64 + mt*16, k0, g, t);
        #pragma unroll
        for (int nt = 0; nt < 2; nt++) ldb_kn(bV[nt], v_s, 68, k0, wc*16 + nt*8, g, t);
        #pragma unroll
        for (int mt = 0; mt < 4; mt++)
            #pragma unroll
            for (int nt = 0; nt < 2; nt++)
                if (k0 <= wr*64 + mt*16 + 15)   // tile rows all-masked beyond diag
                    mma3(CN[mt][nt], a[mt], bV[nt]);
    }
    __syncthreads();

    #pragma unroll
    for (int mt = 0; mt < 4; mt++)
        #pragma unroll
        for (int nt = 0; nt < 2; nt++) {
            int r = wr*64 + mt*16 + g, c = wc*16 + nt*8 + 2*t;
            float den = den1[r] + den2[r];
            den += (fabsf(den) <= 1e-6f) ? 2e-6f : 0.f;
            float inv = 1.f / den;
            *(float2*)&out[(rowbase + (size_t)r * 8) * 64 + c] =
                make_float2(CN[mt][nt][0] * inv, CN[mt][nt][1] * inv);
            float den8 = den1[r+8] + den2[r+8];
            den8 += (fabsf(den8) <= 1e-6f) ? 2e-6f : 0.f;
            float inv8 = 1.f / den8;
            *(float2*)&out[(rowbase + (size_t)(r+8) * 8) * 64 + c] =
                make_float2(CN[mt][nt][2] * inv8, CN[mt][nt][3] * inv8);
        }
}

extern "C" void kernel_launch(void* const* d_in, const int* in_sizes, int n_in,
                              void* d_out, int out_size) {
    const float* q    = (const float*)d_in[0];
    const float* k    = (const float*)d_in[1];
    const float* v    = (const float*)d_in[2];
    const float* proj = (const float*)d_in[3];
    float* out = (float*)d_out;
    (void)in_sizes; (void)n_in; (void)out_size;

    const int SMF = 87040;
    const int SMK = 42624;
    const int SMA = 102400;
    cudaFuncSetAttribute(k_feat,  cudaFuncAttributeMaxDynamicSharedMemorySize, SMF);
    cudaFuncSetAttribute(k_kvblk, cudaFuncAttributeMaxDynamicSharedMemorySize, SMK);
    cudaFuncSetAttribute(k_attn,  cudaFuncAttributeMaxDynamicSharedMemorySize, SMA);

    k_init<<<1, 32>>>();
    k_feat<<<1024, 256, SMF>>>(q, proj, 1);
    k_feat<<<1024, 256, SMF>>>(k, proj, 0);
    k_kfinish<<<16384, 256>>>();
    k_kvblk<<<512, 256, SMK>>>(v);
    k_scan<<<128, 256>>>();
    k_attn<<<512, 256, SMA>>>(v, out);
}

// round 5
// speedup vs baseline: 1.7871x; 1.0321x over previous
#include <cuda_runtime.h>

// B=4, L=2048, H=8, D=64, M=256, chunk T=128, 16 chunks/head
#define NRMc   0.35355339059327373f   // 64^-0.25
#define RATIOc 0.0625f                // 1/sqrt(256)
#define KEPSc  1e-4f

__device__ float g_qp[16777216];   // [65536][256] query features
__device__ float g_kp[16777216];   // [65536][256] key dash -> features (in place)
__device__ float g_kv[8388608];    // [512][256][64] block KV -> exclusive prefix
__device__ float g_s[131072];      // [512][256]    block k-sums -> exclusive prefix
__device__ float g_kmax[32];

__device__ __forceinline__ void atomicMaxFloat(float* addr, float v) {
    if (v >= 0.f) atomicMax((int*)addr, __float_as_int(v));
    else          atomicMin((unsigned int*)addr, __float_as_uint(v));
}

__global__ void k_init() {
    if (threadIdx.x < 32) g_kmax[threadIdx.x] = __int_as_float(0xff800000);
}

// ---------------- 3xTF32 MMA helpers (m16n8k8, row.col) --------------------
__device__ __forceinline__ float2 tfsplit(float x) {
    unsigned h; asm("cvt.rna.tf32.f32 %0, %1;" : "=r"(h) : "f"(x));
    float hf = __uint_as_float(h);
    float r = x - hf;
    unsigned l; asm("cvt.rna.tf32.f32 %0, %1;" : "=r"(l) : "f"(r));
    return make_float2(hf, __uint_as_float(l));
}
__device__ __forceinline__ void f2tf2(float f, unsigned& h, unsigned& l) {
    asm("cvt.rna.tf32.f32 %0, %1;" : "=r"(h) : "f"(f));
    float r = f - __uint_as_float(h);
    asm("cvt.rna.tf32.f32 %0, %1;" : "=r"(l) : "f"(r));
}
struct FA { unsigned h[4]; unsigned l[4]; };
struct FB { unsigned h[2]; unsigned l[2]; };

__device__ __forceinline__ void mma8(float c[4], const unsigned a[4], const unsigned b[2]) {
    asm volatile("mma.sync.aligned.m16n8k8.row.col.f32.tf32.tf32.f32 "
                 "{%0,%1,%2,%3},{%4,%5,%6,%7},{%8,%9},{%0,%1,%2,%3};"
                 : "+f"(c[0]), "+f"(c[1]), "+f"(c[2]), "+f"(c[3])
                 : "r"(a[0]), "r"(a[1]), "r"(a[2]), "r"(a[3]), "r"(b[0]), "r"(b[1]));
}
__device__ __forceinline__ void mma3(float c[4], const FA& a, const FB& b) {
    mma8(c, a.l, b.h);
    mma8(c, a.h, b.l);
    mma8(c, a.h, b.h);
}
// A[r][k] from pre-split row-major H/L [r][k] (pitch P)
__device__ __forceinline__ void ldaHL(FA& a, const float* H, const float* L, int P, int r, int k, int g, int t) {
    a.h[0] = __float_as_uint(H[(r+g)*P + k + t]);
    a.h[1] = __float_as_uint(H[(r+g+8)*P + k + t]);
    a.h[2] = __float_as_uint(H[(r+g)*P + k + t + 4]);
    a.h[3] = __float_as_uint(H[(r+g+8)*P + k + t + 4]);
    a.l[0] = __float_as_uint(L[(r+g)*P + k + t]);
    a.l[1] = __float_as_uint(L[(r+g+8)*P + k + t]);
    a.l[2] = __float_as_uint(L[(r+g)*P + k + t + 4]);
    a.l[3] = __float_as_uint(L[(r+g+8)*P + k + t + 4]);
}
// A[m][k] from pre-split H/L stored [k][m] (pitch P)
__device__ __forceinline__ void ldaHL_t(FA& a, const float* H, const float* L, int P, int r, int k, int g, int t) {
    a.h[0] = __float_as_uint(H[(k+t)*P + r + g]);
    a.h[1] = __float_as_uint(H[(k+t)*P + r + g + 8]);
    a.h[2] = __float_as_uint(H[(k+t+4)*P + r + g]);
    a.h[3] = __float_as_uint(H[(k+t+4)*P + r + g + 8]);
    a.l[0] = __float_as_uint(L[(k+t)*P + r + g]);
    a.l[1] = __float_as_uint(L[(k+t)*P + r + g + 8]);
    a.l[2] = __float_as_uint(L[(k+t+4)*P + r + g]);
    a.l[3] = __float_as_uint(L[(k+t+4)*P + r + g + 8]);
}
// B[k][n] from pre-split H/L stored [n][k] (pitch P)
__device__ __forceinline__ void ldbHL_nk(FB& b, const float* H, const float* L, int P, int n, int k, int g, int t) {
    b.h[0] = __float_as_uint(H[(n+g)*P + k + t]);
    b.h[1] = __float_as_uint(H[(n+g)*P + k + t + 4]);
    b.l[0] = __float_as_uint(L[(n+g)*P + k + t]);
    b.l[1] = __float_as_uint(L[(n+g)*P + k + t + 4]);
}
// B[k][n] from pre-split H/L stored [k][n] (pitch P)
__device__ __forceinline__ void ldbHL_kn(FB& b, const float* H, const float* L, int P, int k, int n, int g, int t) {
    b.h[0] = __float_as_uint(H[(k+t)*P + n + g]);
    b.h[1] = __float_as_uint(H[(k+t+4)*P + n + g]);
    b.l[0] = __float_as_uint(L[(k+t)*P + n + g]);
    b.l[1] = __float_as_uint(L[(k+t+4)*P + n + g]);
}
// B[k][n] on-the-fly split from full-precision S [k][n] (pitch P)
__device__ __forceinline__ void ldb_kn(FB& b, const float* S, int P, int k, int n, int g, int t) {
    f2tf2(S[(k+t)*P + n + g],   b.h[0], b.l[0]);
    f2tf2(S[(k+t+4)*P + n + g], b.h[1], b.l[1]);
}

// ---------------------------------------------------------------------------
// Features: dash[64x256] = (NRM*X)[64x64] @ P^T, per block of 64 rows.
// ---------------------------------------------------------------------------
__global__ __launch_bounds__(256) void k_feat(const float* __restrict__ x,
                                              const float* __restrict__ proj,
                                              int is_query) {
    extern __shared__ float sm[];
    float* qh = sm;              // [64][68]
    float* ql = sm + 4352;       // [64][68]
    float* ph = sm + 8704;       // [256][68]
    float* pl = sm + 26112;      // [256][68]
    float* dash = ph;            // alias after GEMM: [64][257] (16448 <= 17408)
    __shared__ float rmax_s[64];
    __shared__ float diag_s[64];
    __shared__ float pmax[256];

    int tid = threadIdx.x, lane = tid & 31, wid = tid >> 5;
    int g = lane >> 2, t = lane & 3;
    int wr = wid >> 2, wc = wid & 3;
    int n0 = blockIdx.x * 64;
    float* outp = is_query ? g_qp : g_kp;

    for (int idx = tid; idx < 1024; idx += 256) {        // X: scale + split
        int r = idx >> 4, d4 = idx & 15;
        float4 v = *(const float4*)&x[(size_t)(n0 + r) * 64 + d4 * 4];
        float2 sx = tfsplit(NRMc * v.x), sy = tfsplit(NRMc * v.y);
        float2 sz = tfsplit(NRMc * v.z), sw = tfsplit(NRMc * v.w);
        *(float4*)&qh[r*68 + d4*4] = make_float4(sx.x, sy.x, sz.x, sw.x);
        *(float4*)&ql[r*68 + d4*4] = make_float4(sx.y, sy.y, sz.y, sw.y);
    }
    for (int idx = tid; idx < 4096; idx += 256) {        // proj: split
        int m = idx >> 4, d4 = idx & 15;
        float4 v = *(const float4*)&proj[(size_t)m * 64 + d4 * 4];
        float2 sx = tfsplit(v.x), sy = tfsplit(v.y);
        float2 sz = tfsplit(v.z), sw = tfsplit(v.w);
        *(float4*)&ph[m*68 + d4*4] = make_float4(sx.x, sy.x, sz.x, sw.x);
        *(float4*)&pl[m*68 + d4*4] = make_float4(sx.y, sy.y, sz.y, sw.y);
    }
    __syncthreads();

    if (tid < 64) {      // diag = 0.5*||NRM*x||^2  (h+l reconstruct, err ~2^-22)
        float ssum = 0.f;
        #pragma unroll
        for (int i = 0; i < 16; i++) {
            float4 h4 = *(float4*)&qh[tid*68 + i*4];
            float4 l4 = *(float4*)&ql[tid*68 + i*4];
            float a = h4.x + l4.x, b = h4.y + l4.y, c = h4.z + l4.z, d = h4.w + l4.w;
            ssum += a*a + b*b + c*c + d*d;
        }
        diag_s[tid] = 0.5f * ssum;
    }

    float C[2][8][4];
    #pragma unroll
    for (int mt = 0; mt < 2; mt++)
        #pragma unroll
        for (int nt = 0; nt < 8; nt++)
            #pragma unroll
            for (int i = 0; i < 4; i++) C[mt][nt][i] = 0.f;

    #pragma unroll 1
    for (int k0 = 0; k0 < 64; k0 += 8) {
        FA a[2]; FB b[8];
        #pragma unroll
        for (int mt = 0; mt < 2; mt++) ldaHL(a[mt], qh, ql, 68, wr*32 + mt*16, k0, g, t);
        #pragma unroll
        for (int nt = 0; nt < 8; nt++) ldbHL_nk(b[nt], ph, pl, 68, wc*64 + nt*8, k0, g, t);
        #pragma unroll
        for (int mt = 0; mt < 2; mt++)
            #pragma unroll
            for (int nt = 0; nt < 8; nt++) mma3(C[mt][nt], a[mt], b[nt]);
    }
    __syncthreads();   // ph/pl reads done; alias as dash

    #pragma unroll
    for (int mt = 0; mt < 2; mt++)
        #pragma unroll
        for (int nt = 0; nt < 8; nt++) {
            int r = wr*32 + mt*16 + g, c = wc*64 + nt*8 + 2*t;
            dash[r*257 + c]       = C[mt][nt][0];
            dash[r*257 + c + 1]   = C[mt][nt][1];
            dash[(r+8)*257 + c]   = C[mt][nt][2];
            dash[(r+8)*257 + c+1] = C[mt][nt][3];
        }
    __syncthreads();

    {   // row max: 4 threads per row, staggered to dodge conflicts
        int row = tid >> 2, part = tid & 3;
        float mx = __int_as_float(0xff800000);
        const float* dr = &dash[row*257 + part*64];
        #pragma unroll 4
        for (int i = 0; i < 64; i++) {
            int ii = (i + part*16) & 63;
            mx = fmaxf(mx, dr[ii]);
        }
        pmax[tid] = mx;
    }
    __syncthreads();
    if (tid < 64) {
        float mx = fmaxf(fmaxf(pmax[tid*4], pmax[tid*4+1]),
                         fmaxf(pmax[tid*4+2], pmax[tid*4+3]));
        rmax_s[tid] = mx;
        if (!is_query) {
            int n = n0 + tid;
            atomicMaxFloat(&g_kmax[((n >> 14) << 3) | (n & 7)], mx);
        }
    }
    __syncthreads();

    int m = tid;
    #pragma unroll 1
    for (int r = 0; r < 64; r++) {
        float val = dash[r*257 + m] - diag_s[r];
        if (is_query) val = RATIOc * (expf(val - rmax_s[r]) + KEPSc);
        outp[(size_t)(n0 + r) * 256 + m] = val;
    }
}

// ---------------------------------------------------------------------------
// Per-chunk KV[256x64] = Kp^T @ V, S[256] = colsum(Kp). Fuses key exp:
// reads dash-diag from g_kp, writes finished features back. grid = 512.
// ---------------------------------------------------------------------------
__global__ __launch_bounds__(256) void k_kvblk(const float* __restrict__ v) {
    extern __shared__ float sm[];
    float* kph = sm;             // [32][260]
    float* kpl = sm + 8320;      // [32][260]
    float* vh  = sm + 16640;     // [32][68]
    float* vl  = sm + 18816;     // [32][68]

    int tid = threadIdx.x, lane = tid & 31, wid = tid >> 5;
    int g = lane >> 2, t = lane & 3;
    int wr = wid >> 1, wc = wid & 1;
    int bh = blockIdx.x >> 4, j = blockIdx.x & 15;
    int b = bh >> 3, h = bh & 7;
    size_t rowbase = (size_t)(b * 2048 + j * 128) * 8 + h;
    float st = g_kmax[bh];

    float C[4][4][4];
    #pragma unroll
    for (int mt = 0; mt < 4; mt++)
        #pragma unroll
        for (int nt = 0; nt < 4; nt++)
            #pragma unroll
            for (int i = 0; i < 4; i++) C[mt][nt][i] = 0.f;
    float ssum = 0.f;

    #pragma unroll 1
    for (int uc = 0; uc < 4; uc++) {
        __syncthreads();
        for (int idx = tid; idx < 2048; idx += 256) {   // kp: exp + writeback + split
            int u = idx >> 6, m4 = idx & 63;
            size_t gaddr = (rowbase + (size_t)(uc*32 + u) * 8) * 256 + m4*4;
            float4 x = *(const float4*)&g_kp[gaddr];
            x.x = RATIOc * (expf(x.x - st) + KEPSc);
            x.y = RATIOc * (expf(x.y - st) + KEPSc);
            x.z = RATIOc * (expf(x.z - st) + KEPSc);
            x.w = RATIOc * (expf(x.w - st) + KEPSc);
            *(float4*)&g_kp[gaddr] = x;
            float2 sx = tfsplit(x.x), sy = tfsplit(x.y);
            float2 sz = tfsplit(x.z), sw = tfsplit(x.w);
            *(float4*)&kph[u*260 + m4*4] = make_float4(sx.x, sy.x, sz.x, sw.x);
            *(float4*)&kpl[u*260 + m4*4] = make_float4(sx.y, sy.y, sz.y, sw.y);
        }
        for (int idx = tid; idx < 512; idx += 256) {    // v: split
            int u = idx >> 4, d4 = idx & 15;
            float4 x = *(const float4*)&v[(rowbase + (size_t)(uc*32 + u) * 8) * 64 + d4*4];
            float2 sx = tfsplit(x.x), sy = tfsplit(x.y);
            float2 sz = tfsplit(x.z), sw = tfsplit(x.w);
            *(float4*)&vh[u*68 + d4*4] = make_float4(sx.x, sy.x, sz.x, sw.x);
            *(float4*)&vl[u*68 + d4*4] = make_float4(sx.y, sy.y, sz.y, sw.y);
        }
        __syncthreads();

        #pragma unroll
        for (int u = 0; u < 32; u++) ssum += kph[u*260 + tid] + kpl[u*260 + tid];

        #pragma unroll
        for (int k0 = 0; k0 < 32; k0 += 8) {
            FA a[4]; FB bv[4];
            #pragma unroll
            for (int mt = 0; mt < 4; mt++) ldaHL_t(a[mt], kph, kpl, 260, wr*64 + mt*16, k0, g, t);
            #pragma unroll
            for (int nt = 0; nt < 4; nt++) ldbHL_kn(bv[nt], vh, vl, 68, k0, wc*32 + nt*8, g, t);
            #pragma unroll
            for (int mt = 0; mt < 4; mt++)
                #pragma unroll
                for (int nt = 0; nt < 4; nt++) mma3(C[mt][nt], a[mt], bv[nt]);
        }
    }

    float* o = &g_kv[(size_t)blockIdx.x * 16384];
    #pragma unroll
    for (int mt = 0; mt < 4; mt++)
        #pragma unroll
        for (int nt = 0; nt < 4; nt++) {
            int m = wr*64 + mt*16 + g, d = wc*32 + nt*8 + 2*t;
            *(float2*)&o[m*64 + d]     = make_float2(C[mt][nt][0], C[mt][nt][1]);
            *(float2*)&o[(m+8)*64 + d] = make_float2(C[mt][nt][2], C[mt][nt][3]);
        }
    g_s[blockIdx.x * 256 + tid] = ssum;
}

// Exclusive prefix over 16 chunks/head, in place. grid = 128.
__global__ void k_scan() {
    int bh = blockIdx.x >> 2, c = blockIdx.x & 3;
    int d0 = c * 16;
    int m = threadIdx.x;
    float run[16];
    #pragma unroll
    for (int k = 0; k < 16; k++) run[k] = 0.f;
    for (int j = 0; j < 16; j++) {
        float* p = &g_kv[((size_t)(bh*16 + j) * 256 + m) * 64 + d0];
        #pragma unroll
        for (int k4 = 0; k4 < 4; k4++) {
            float4 v = *(float4*)&p[k4*4];
            *(float4*)&p[k4*4] = make_float4(run[k4*4], run[k4*4+1], run[k4*4+2], run[k4*4+3]);
            run[k4*4] += v.x; run[k4*4+1] += v.y; run[k4*4+2] += v.z; run[k4*4+3] += v.w;
        }
    }
    if (c == 0) {
        float rs = 0.f;
        for (int j = 0; j < 16; j++) {
            size_t idx = (size_t)(bh*16 + j) * 256 + m;
            float v = g_s[idx]; g_s[idx] = rs; rs += v;
        }
    }
}

// ---------------------------------------------------------------------------
// Attention block: A = Qp Kp^T, NP = Qp P_prev, AV = tril(A) V,
// den = Qp.S_prev + rowsum(tril A). grid = 512.
// ---------------------------------------------------------------------------
__global__ __launch_bounds__(256, 1) void k_attn(const float* __restrict__ v,
                                                 float* __restrict__ out) {
    extern __shared__ float sm[];
    // Phase 2 layout
    float* Ah  = sm;             // [128][132]
    float* Al  = sm + 16896;     // [128][132]
    float* v_s = sm + 33792;     // [128][68] (persists through phase 1)
    // Phase 1 aliases inside [0, 33792)
    float* qph = sm;             // [128][36]
    float* qpl = sm + 4608;
    float* kph = sm + 9216;
    float* kpl = sm + 13824;
    float* psh = sm + 18432;     // [32][68]
    float* psl = sm + 20608;
    __shared__ float Ss_s[32];
    __shared__ float den1[128], den2[128];

    int tid = threadIdx.x, lane = tid & 31, wid = tid >> 5;
    int g = lane >> 2, t = lane & 3;
    int wr = wid >> 2, wc = wid & 3;
    int bh = blockIdx.x >> 4, j = blockIdx.x & 15;
    int b = bh >> 3, h = bh & 7;
    size_t rowbase = (size_t)(b * 2048 + j * 128) * 8 + h;

    float CA[4][4][4];
    float CN[4][2][4];
    #pragma unroll
    for (int mt = 0; mt < 4; mt++) {
        #pragma unroll
        for (int nt = 0; nt < 4; nt++)
            #pragma unroll
            for (int i = 0; i < 4; i++) CA[mt][nt][i] = 0.f;
        #pragma unroll
        for (int nt = 0; nt < 2; nt++)
            #pragma unroll
            for (int i = 0; i < 4; i++) CN[mt][nt][i] = 0.f;
    }
    float denq = 0.f;

    #pragma unroll 1
    for (int kc = 0; kc < 8; kc++) {
        __syncthreads();
        for (int idx = tid; idx < 1024; idx += 256) {   // qp chunk: split
            int r = idx >> 3, k4 = idx & 7;
            float4 x = *(const float4*)&g_qp[(rowbase + (size_t)r * 8) * 256 + kc*32 + k4*4];
            float2 sx = tfsplit(x.x), sy = tfsplit(x.y);
            float2 sz = tfsplit(x.z), sw = tfsplit(x.w);
            *(float4*)&qph[r*36 + k4*4] = make_float4(sx.x, sy.x, sz.x, sw.x);
            *(float4*)&qpl[r*36 + k4*4] = make_float4(sx.y, sy.y, sz.y, sw.y);
        }
        for (int idx = tid; idx < 1024; idx += 256) {   // kp chunk: split
            int r = idx >> 3, k4 = idx & 7;
            float4 x = *(const float4*)&g_kp[(rowbase + (size_t)r * 8) * 256 + kc*32 + k4*4];
            float2 sx = tfsplit(x.x), sy = tfsplit(x.y);
            float2 sz = tfsplit(x.z), sw = tfsplit(x.w);
            *(float4*)&kph[r*36 + k4*4] = make_float4(sx.x, sy.x, sz.x, sw.x);
            *(float4*)&kpl[r*36 + k4*4] = make_float4(sx.y, sy.y, sz.y, sw.y);
        }
        for (int idx = tid; idx < 512; idx += 256) {    // Ps chunk: split
            int kk = idx >> 4, d4 = idx & 15;
            float4 x = *(const float4*)&g_kv[(size_t)blockIdx.x * 16384 + (kc*32 + kk)*64 + d4*4];
            float2 sx = tfsplit(x.x), sy = tfsplit(x.y);
            float2 sz = tfsplit(x.z), sw = tfsplit(x.w);
            *(float4*)&psh[kk*68 + d4*4] = make_float4(sx.x, sy.x, sz.x, sw.x);
            *(float4*)&psl[kk*68 + d4*4] = make_float4(sx.y, sy.y, sz.y, sw.y);
        }
        if (tid < 32) Ss_s[tid] = g_s[blockIdx.x * 256 + kc*32 + tid];
        if (kc == 0) {
            for (int idx = tid; idx < 2048; idx += 256) {   // V [128][64], full precision
                int u = idx >> 4, d4 = idx & 15;
                *(float4*)&v_s[u*68 + d4*4] =
                    *(const float4*)&v[(rowbase + (size_t)u * 8) * 64 + d4*4];
            }
        }
        __syncthreads();

        #pragma unroll
        for (int k0 = 0; k0 < 32; k0 += 8) {
            FA a[4]; FB bA[4], bP[2];
            #pragma unroll
            for (int mt = 0; mt < 4; mt++) ldaHL(a[mt], qph, qpl, 36, wr*64 + mt*16, k0, g, t);
            #pragma unroll
            for (int nt = 0; nt < 4; nt++) ldbHL_nk(bA[nt], kph, kpl, 36, wc*32 + nt*8, k0, g, t);
            #pragma unroll
            for (int nt = 0; nt < 2; nt++) ldbHL_kn(bP[nt], psh, psl, 68, k0, wc*16 + nt*8, g, t);
            #pragma unroll
            for (int mt = 0; mt < 4; mt++) {
                #pragma unroll
                for (int nt = 0; nt < 4; nt++)
                    if (wc*32 + nt*8 <= wr*64 + mt*16 + 15)   // skip fully-masked tiles
                        mma3(CA[mt][nt], a[mt], bA[nt]);
                #pragma unroll
                for (int nt = 0; nt < 2; nt++) mma3(CN[mt][nt], a[mt], bP[nt]);
            }
        }
        if (tid < 128) {
            #pragma unroll
            for (int kk = 0; kk < 32; kk++)
                denq += (qph[tid*36 + kk] + qpl[tid*36 + kk]) * Ss_s[kk];
        }
    }
    __syncthreads();   // phase-1 smem dead; alias Ah/Al

    #pragma unroll
    for (int mt = 0; mt < 4; mt++)
        #pragma unroll
        for (int nt = 0; nt < 4; nt++) {
            int r = wr*64 + mt*16 + g, c = wc*32 + nt*8 + 2*t;
            float a0 = (c   <= r)   ? CA[mt][nt][0] : 0.f;
            float a1 = (c+1 <= r)   ? CA[mt][nt][1] : 0.f;
            float a2 = (c   <= r+8) ? CA[mt][nt][2] : 0.f;
            float a3 = (c+1 <= r+8) ? CA[mt][nt][3] : 0.f;
            float2 s0 = tfsplit(a0), s1 = tfsplit(a1), s2 = tfsplit(a2), s3 = tfsplit(a3);
            *(float2*)&Ah[r*132 + c]     = make_float2(s0.x, s1.x);
            *(float2*)&Al[r*132 + c]     = make_float2(s0.y, s1.y);
            *(float2*)&Ah[(r+8)*132 + c] = make_float2(s2.x, s3.x);
            *(float2*)&Al[(r+8)*132 + c] = make_float2(s2.y, s3.y);
        }
    if (tid < 128) den1[tid] = denq;
    __syncthreads();

    if (tid < 128) {
        float rs = 0.f;
        #pragma unroll
        for (int u = 0; u < 128; u++) rs += Ah[tid*132 + u] + Al[tid*132 + u];
        den2[tid] = rs;
    }

    int kmax = wr*64 + 64;   // rows in this warp-row need u <= wr*64+63
    #pragma unroll 1
    for (int k0 = 0; k0 < kmax; k0 += 8) {
        FA a[4]; FB bV[2];
        #pragma unroll
        for (int mt = 0; mt < 4; mt++) ldaHL(a[mt], Ah, Al, 132, wr*64 + mt*16, k0, g, t);
        #pragma unroll
        for (int nt = 0; nt < 2; nt++) ldb_kn(bV[nt], v_s, 68, k0, wc*16 + nt*8, g, t);
        #pragma unroll
        for (int mt = 0; mt < 4; mt++)
            #pragma unroll
            for (int nt = 0; nt < 2; nt++)
                if (k0 <= wr*64 + mt*16 + 15)
                    mma3(CN[mt][nt], a[mt], bV[nt]);
    }
    __syncthreads();

    #pragma unroll
    for (int mt = 0; mt < 4; mt++)
        #pragma unroll
        for (int nt = 0; nt < 2; nt++) {
            int r = wr*64 + mt*16 + g, c = wc*16 + nt*8 + 2*t;
            float den = den1[r] + den2[r];
            den += (fabsf(den) <= 1e-6f) ? 2e-6f : 0.f;
            float inv = 1.f / den;
            *(float2*)&out[(rowbase + (size_t)r * 8) * 64 + c] =
                make_float2(CN[mt][nt][0] * inv, CN[mt][nt][1] * inv);
            float den8 = den1[r+8] + den2[r+8];
            den8 += (fabsf(den8) <= 1e-6f) ? 2e-6f : 0.f;
            float inv8 = 1.f / den8;
            *(float2*)&out[(rowbase + (size_t)(r+8) * 8) * 64 + c] =
                make_float2(CN[mt][nt][2] * inv8, CN[mt][nt][3] * inv8);
        }
}

extern "C" void kernel_launch(void* const* d_in, const int* in_sizes, int n_in,
                              void* d_out, int out_size) {
    const float* q    = (const float*)d_in[0];
    const float* k    = (const float*)d_in[1];
    const float* v    = (const float*)d_in[2];
    const float* proj = (const float*)d_in[3];
    float* out = (float*)d_out;
    (void)in_sizes; (void)n_in; (void)out_size;

    const int SMF = 174080;   // k_feat:  43520 floats
    const int SMK = 83968;    // k_kvblk: 20992 floats
    const int SMA = 169984;   // k_attn:  42496 floats
    cudaFuncSetAttribute(k_feat,  cudaFuncAttributeMaxDynamicSharedMemorySize, SMF);
    cudaFuncSetAttribute(k_kvblk, cudaFuncAttributeMaxDynamicSharedMemorySize, SMK);
    cudaFuncSetAttribute(k_attn,  cudaFuncAttributeMaxDynamicSharedMemorySize, SMA);

    k_init<<<1, 32>>>();
    k_feat<<<1024, 256, SMF>>>(q, proj, 1);
    k_feat<<<1024, 256, SMF>>>(k, proj, 0);
    k_kvblk<<<512, 256, SMK>>>(v);
    k_scan<<<128, 256>>>();
    k_attn<<<512, 256, SMA>>>(v, out);
}

// round 7
// speedup vs baseline: 2.3851x; 1.3346x over previous
#include <cuda_runtime.h>

// B=4, L=2048, H=8, D=64, M=256, chunk T=128, 16 chunks/head
#define NRMc   0.35355339059327373f   // 64^-0.25
#define RATIOc 0.0625f                // 1/sqrt(256)
#define KEPSc  1e-4f

__device__ float g_qp[16777216];   // [65536][256] query features
__device__ float g_kp[16777216];   // [65536][256] key dash -> features (in place)
__device__ float g_kv[8388608];    // [512][256][64] block KV -> exclusive prefix
__device__ float g_s[131072];      // [512][256]    block k-sums -> exclusive prefix
__device__ float g_kmax[32];

__device__ __forceinline__ void atomicMaxFloat(float* addr, float v) {
    if (v >= 0.f) atomicMax((int*)addr, __float_as_int(v));
    else          atomicMin((unsigned int*)addr, __float_as_uint(v));
}

__global__ void k_init() {
    if (threadIdx.x < 32) g_kmax[threadIdx.x] = __int_as_float(0xff800000);
}

// ---------------- 3xTF32 MMA helpers (m16n8k8, row.col) --------------------
__device__ __forceinline__ float2 tfsplit(float x) {
    unsigned h; asm("cvt.rna.tf32.f32 %0, %1;" : "=r"(h) : "f"(x));
    float hf = __uint_as_float(h);
    float r = x - hf;
    unsigned l; asm("cvt.rna.tf32.f32 %0, %1;" : "=r"(l) : "f"(r));
    return make_float2(hf, __uint_as_float(l));
}
__device__ __forceinline__ void f2tf2(float f, unsigned& h, unsigned& l) {
    asm("cvt.rna.tf32.f32 %0, %1;" : "=r"(h) : "f"(f));
    float r = f - __uint_as_float(h);
    asm("cvt.rna.tf32.f32 %0, %1;" : "=r"(l) : "f"(r));
}
struct FA { unsigned h[4]; unsigned l[4]; };
struct FB { unsigned h[2]; unsigned l[2]; };

__device__ __forceinline__ void mma8(float c[4], const unsigned a[4], const unsigned b[2]) {
    asm volatile("mma.sync.aligned.m16n8k8.row.col.f32.tf32.tf32.f32 "
                 "{%0,%1,%2,%3},{%4,%5,%6,%7},{%8,%9},{%0,%1,%2,%3};"
                 : "+f"(c[0]), "+f"(c[1]), "+f"(c[2]), "+f"(c[3])
                 : "r"(a[0]), "r"(a[1]), "r"(a[2]), "r"(a[3]), "r"(b[0]), "r"(b[1]));
}
__device__ __forceinline__ void mma3(float c[4], const FA& a, const FB& b) {
    mma8(c, a.l, b.h);
    mma8(c, a.h, b.l);
    mma8(c, a.h, b.h);
}
// A[r][k] from pre-split row-major H/L [r][k] (pitch P)
__device__ __forceinline__ void ldaHL(FA& a, const float* H, const float* L, int P, int r, int k, int g, int t) {
    a.h[0] = __float_as_uint(H[(r+g)*P + k + t]);
    a.h[1] = __float_as_uint(H[(r+g+8)*P + k + t]);
    a.h[2] = __float_as_uint(H[(r+g)*P + k + t + 4]);
    a.h[3] = __float_as_uint(H[(r+g+8)*P + k + t + 4]);
    a.l[0] = __float_as_uint(L[(r+g)*P + k + t]);
    a.l[1] = __float_as_uint(L[(r+g+8)*P + k + t]);
    a.l[2] = __float_as_uint(L[(r+g)*P + k + t + 4]);
    a.l[3] = __float_as_uint(L[(r+g+8)*P + k + t + 4]);
}
// A[m][k] from pre-split H/L stored [k][m] (pitch P)
__device__ __forceinline__ void ldaHL_t(FA& a, const float* H, const float* L, int P, int r, int k, int g, int t) {
    a.h[0] = __float_as_uint(H[(k+t)*P + r + g]);
    a.h[1] = __float_as_uint(H[(k+t)*P + r + g + 8]);
    a.h[2] = __float_as_uint(H[(k+t+4)*P + r + g]);
    a.h[3] = __float_as_uint(H[(k+t+4)*P + r + g + 8]);
    a.l[0] = __float_as_uint(L[(k+t)*P + r + g]);
    a.l[1] = __float_as_uint(L[(k+t)*P + r + g + 8]);
    a.l[2] = __float_as_uint(L[(k+t+4)*P + r + g]);
    a.l[3] = __float_as_uint(L[(k+t+4)*P + r + g + 8]);
}
// B[k][n] from pre-split H/L stored [n][k] (pitch P)
__device__ __forceinline__ void ldbHL_nk(FB& b, const float* H, const float* L, int P, int n, int k, int g, int t) {
    b.h[0] = __float_as_uint(H[(n+g)*P + k + t]);
    b.h[1] = __float_as_uint(H[(n+g)*P + k + t + 4]);
    b.l[0] = __float_as_uint(L[(n+g)*P + k + t]);
    b.l[1] = __float_as_uint(L[(n+g)*P + k + t + 4]);
}
// B[k][n] from pre-split H/L stored [k][n] (pitch P)
__device__ __forceinline__ void ldbHL_kn(FB& b, const float* H, const float* L, int P, int k, int n, int g, int t) {
    b.h[0] = __float_as_uint(H[(k+t)*P + n + g]);
    b.h[1] = __float_as_uint(H[(k+t+4)*P + n + g]);
    b.l[0] = __float_as_uint(L[(k+t)*P + n + g]);
    b.l[1] = __float_as_uint(L[(k+t+4)*P + n + g]);
}
// on-the-fly split loaders from full-precision smem
__device__ __forceinline__ void ldbF_nk(FB& b, const float* S, int P, int n, int k, int g, int t) {
    f2tf2(S[(n+g)*P + k + t],     b.h[0], b.l[0]);
    f2tf2(S[(n+g)*P + k + t + 4], b.h[1], b.l[1]);
}
__device__ __forceinline__ void ldbF_kn(FB& b, const float* S, int P, int k, int n, int g, int t) {
    f2tf2(S[(k+t)*P + n + g],   b.h[0], b.l[0]);
    f2tf2(S[(k+t+4)*P + n + g], b.h[1], b.l[1]);
}

// ---------------------------------------------------------------------------
// Features: dash[64x256] = (NRM*X)[64x64] @ P^T. 512 thr, 16 warps (2x8).
// smem 104.4KB: X pre-split, proj full-precision (B split on the fly).
// ---------------------------------------------------------------------------
__global__ __launch_bounds__(512) void k_feat(const float* __restrict__ x,
                                              const float* __restrict__ proj,
                                              int is_query) {
    extern __shared__ float sm[];
    float* qh  = sm;             // [64][68]
    float* ql  = sm + 4352;      // [64][68]
    float* p_s = sm + 8704;      // [256][68] fp32
    float* dash = p_s;           // alias after GEMM: [64][257] (16448 <= 17408)
    __shared__ float rmax_s[64];
    __shared__ float diag_s[64];
    __shared__ float pmax[512];

    int tid = threadIdx.x, lane = tid & 31, wid = tid >> 5;
    int g = lane >> 2, t = lane & 3;
    int wr = wid >> 3, wc = wid & 7;       // 2 x 8 warps: 32 rows x 32 cols each
    int n0 = blockIdx.x * 64;
    float* outp = is_query ? g_qp : g_kp;

    for (int idx = tid; idx < 1024; idx += 512) {        // X: scale + split
        int r = idx >> 4, d4 = idx & 15;
        float4 v = *(const float4*)&x[(size_t)(n0 + r) * 64 + d4 * 4];
        float2 sx = tfsplit(NRMc * v.x), sy = tfsplit(NRMc * v.y);
        float2 sz = tfsplit(NRMc * v.z), sw = tfsplit(NRMc * v.w);
        *(float4*)&qh[r*68 + d4*4] = make_float4(sx.x, sy.x, sz.x, sw.x);
        *(float4*)&ql[r*68 + d4*4] = make_float4(sx.y, sy.y, sz.y, sw.y);
    }
    for (int idx = tid; idx < 4096; idx += 512) {        // proj copy (fp32)
        int m = idx >> 4, d4 = idx & 15;
        *(float4*)&p_s[m*68 + d4*4] = *(const float4*)&proj[(size_t)m * 64 + d4 * 4];
    }
    __syncthreads();

    if (tid < 64) {      // diag = 0.5*||NRM*x||^2 (h+l reconstruct)
        float ssum = 0.f;
        #pragma unroll
        for (int i = 0; i < 16; i++) {
            float4 h4 = *(float4*)&qh[tid*68 + i*4];
            float4 l4 = *(float4*)&ql[tid*68 + i*4];
            float a = h4.x + l4.x, b = h4.y + l4.y, c = h4.z + l4.z, d = h4.w + l4.w;
            ssum += a*a + b*b + c*c + d*d;
        }
        diag_s[tid] = 0.5f * ssum;
    }

    float C[2][4][4];
    #pragma unroll
    for (int mt = 0; mt < 2; mt++)
        #pragma unroll
        for (int nt = 0; nt < 4; nt++)
            #pragma unroll
            for (int i = 0; i < 4; i++) C[mt][nt][i] = 0.f;

    #pragma unroll 1
    for (int k0 = 0; k0 < 64; k0 += 8) {
        FA a[2]; FB b[4];
        #pragma unroll
        for (int mt = 0; mt < 2; mt++) ldaHL(a[mt], qh, ql, 68, wr*32 + mt*16, k0, g, t);
        #pragma unroll
        for (int nt = 0; nt < 4; nt++) ldbF_nk(b[nt], p_s, 68, wc*32 + nt*8, k0, g, t);
        #pragma unroll
        for (int mt = 0; mt < 2; mt++)
            #pragma unroll
            for (int nt = 0; nt < 4; nt++) mma3(C[mt][nt], a[mt], b[nt]);
    }
    __syncthreads();   // p_s reads done; alias as dash

    #pragma unroll
    for (int mt = 0; mt < 2; mt++)
        #pragma unroll
        for (int nt = 0; nt < 4; nt++) {
            int r = wr*32 + mt*16 + g, c = wc*32 + nt*8 + 2*t;
            dash[r*257 + c]       = C[mt][nt][0];
            dash[r*257 + c + 1]   = C[mt][nt][1];
            dash[(r+8)*257 + c]   = C[mt][nt][2];
            dash[(r+8)*257 + c+1] = C[mt][nt][3];
        }
    __syncthreads();

    {   // row max: 8 threads per row, staggered
        int row = tid >> 3, part = tid & 7;
        float mx = __int_as_float(0xff800000);
        const float* dr = &dash[row*257 + part*32];
        #pragma unroll 4
        for (int i = 0; i < 32; i++) {
            int ii = (i + part*4) & 31;
            mx = fmaxf(mx, dr[ii]);
        }
        pmax[tid] = mx;
    }
    __syncthreads();
    if (tid < 64) {
        float mx = pmax[tid*8];
        #pragma unroll
        for (int p = 1; p < 8; p++) mx = fmaxf(mx, pmax[tid*8 + p]);
        rmax_s[tid] = mx;
        if (!is_query) {
            int n = n0 + tid;
            atomicMaxFloat(&g_kmax[((n >> 14) << 3) | (n & 7)], mx);
        }
    }
    __syncthreads();

    int m = tid & 255, rh = tid >> 8;
    #pragma unroll 1
    for (int r = rh*32; r < rh*32 + 32; r++) {
        float val = dash[r*257 + m] - diag_s[r];
        if (is_query) val = RATIOc * (expf(val - rmax_s[r]) + KEPSc);
        outp[(size_t)(n0 + r) * 256 + m] = val;
    }
}

// ---------------------------------------------------------------------------
// Per-chunk KV[256x64] = Kp^T @ V, S[256] = colsum(Kp). Fused key exp.
// 512 thr, 16 warps (4x4): 64 rows x 16 cols each. grid = 512.
// ---------------------------------------------------------------------------
__global__ __launch_bounds__(512) void k_kvblk(const float* __restrict__ v) {
    extern __shared__ float sm[];
    float* kph = sm;             // [32][260]
    float* kpl = sm + 8320;      // [32][260]
    float* vh  = sm + 16640;     // [32][68]
    float* vl  = sm + 18816;     // [32][68]
    __shared__ float ssum2[512];

    int tid = threadIdx.x, lane = tid & 31, wid = tid >> 5;
    int g = lane >> 2, t = lane & 3;
    int wr = wid >> 2, wc = wid & 3;     // 4 x 4 warps
    int bh = blockIdx.x >> 4, j = blockIdx.x & 15;
    int b = bh >> 3, h = bh & 7;
    size_t rowbase = (size_t)(b * 2048 + j * 128) * 8 + h;
    float st = g_kmax[bh];

    float C[4][2][4];
    #pragma unroll
    for (int mt = 0; mt < 4; mt++)
        #pragma unroll
        for (int nt = 0; nt < 2; nt++)
            #pragma unroll
            for (int i = 0; i < 4; i++) C[mt][nt][i] = 0.f;
    float ssum = 0.f;
    int scol = tid & 255, uh = tid >> 8;   // 2 threads per column, 16 u's each

    #pragma unroll 1
    for (int uc = 0; uc < 4; uc++) {
        __syncthreads();
        for (int idx = tid; idx < 2048; idx += 512) {   // kp: exp + writeback + split
            int u = idx >> 6, m4 = idx & 63;
            size_t gaddr = (rowbase + (size_t)(uc*32 + u) * 8) * 256 + m4*4;
            float4 x = *(const float4*)&g_kp[gaddr];
            x.x = RATIOc * (expf(x.x - st) + KEPSc);
            x.y = RATIOc * (expf(x.y - st) + KEPSc);
            x.z = RATIOc * (expf(x.z - st) + KEPSc);
            x.w = RATIOc * (expf(x.w - st) + KEPSc);
            *(float4*)&g_kp[gaddr] = x;
            float2 sx = tfsplit(x.x), sy = tfsplit(x.y);
            float2 sz = tfsplit(x.z), sw = tfsplit(x.w);
            *(float4*)&kph[u*260 + m4*4] = make_float4(sx.x, sy.x, sz.x, sw.x);
            *(float4*)&kpl[u*260 + m4*4] = make_float4(sx.y, sy.y, sz.y, sw.y);
        }
        for (int idx = tid; idx < 512; idx += 512) {    // v: split
            int u = idx >> 4, d4 = idx & 15;
            float4 x = *(const float4*)&v[(rowbase + (size_t)(uc*32 + u) * 8) * 64 + d4*4];
            float2 sx = tfsplit(x.x), sy = tfsplit(x.y);
            float2 sz = tfsplit(x.z), sw = tfsplit(x.w);
            *(float4*)&vh[u*68 + d4*4] = make_float4(sx.x, sy.x, sz.x, sw.x);
            *(float4*)&vl[u*68 + d4*4] = make_float4(sx.y, sy.y, sz.y, sw.y);
        }
        __syncthreads();

        #pragma unroll
        for (int u = uh*16; u < uh*16 + 16; u++)
            ssum += kph[u*260 + scol] + kpl[u*260 + scol];

        #pragma unroll
        for (int k0 = 0; k0 < 32; k0 += 8) {
            FA a[4]; FB bv[2];
            #pragma unroll
            for (int mt = 0; mt < 4; mt++) ldaHL_t(a[mt], kph, kpl, 260, wr*64 + mt*16, k0, g, t);
            #pragma unroll
            for (int nt = 0; nt < 2; nt++) ldbHL_kn(bv[nt], vh, vl, 68, k0, wc*16 + nt*8, g, t);
            #pragma unroll
            for (int mt = 0; mt < 4; mt++)
                #pragma unroll
                for (int nt = 0; nt < 2; nt++) mma3(C[mt][nt], a[mt], bv[nt]);
        }
    }

    float* o = &g_kv[(size_t)blockIdx.x * 16384];
    #pragma unroll
    for (int mt = 0; mt < 4; mt++)
        #pragma unroll
        for (int nt = 0; nt < 2; nt++) {
            int m = wr*64 + mt*16 + g, d = wc*16 + nt*8 + 2*t;
            *(float2*)&o[m*64 + d]     = make_float2(C[mt][nt][0], C[mt][nt][1]);
            *(float2*)&o[(m+8)*64 + d] = make_float2(C[mt][nt][2], C[mt][nt][3]);
        }
    ssum2[tid] = ssum;
    __syncthreads();
    if (tid < 256) g_s[blockIdx.x * 256 + tid] = ssum2[tid] + ssum2[tid + 256];
}

// Exclusive prefix over 16 chunks/head, in place. grid = 128.
__global__ void k_scan() {
    int bh = blockIdx.x >> 2, c = blockIdx.x & 3;
    int d0 = c * 16;
    int m = threadIdx.x;
    float run[16];
    #pragma unroll
    for (int k = 0; k < 16; k++) run[k] = 0.f;
    for (int j = 0; j < 16; j++) {
        float* p = &g_kv[((size_t)(bh*16 + j) * 256 + m) * 64 + d0];
        #pragma unroll
        for (int k4 = 0; k4 < 4; k4++) {
            float4 v = *(float4*)&p[k4*4];
            *(float4*)&p[k4*4] = make_float4(run[k4*4], run[k4*4+1], run[k4*4+2], run[k4*4+3]);
            run[k4*4] += v.x; run[k4*4+1] += v.y; run[k4*4+2] += v.z; run[k4*4+3] += v.w;
        }
    }
    if (c == 0) {
        float rs = 0.f;
        for (int j = 0; j < 16; j++) {
            size_t idx = (size_t)(bh*16 + j) * 256 + m;
            float v = g_s[idx]; g_s[idx] = rs; rs += v;
        }
    }
}

// ---------------------------------------------------------------------------
// Attention block. 512 thr, 16 warps (2x8): A tiles 64x16, NP tiles 64x8.
// grid = 512.
// ---------------------------------------------------------------------------
__global__ __launch_bounds__(512) void k_attn(const float* __restrict__ v,
                                              float* __restrict__ out) {
    extern __shared__ float sm[];
    // Phase 2 layout
    float* Ah  = sm;             // [128][132]
    float* Al  = sm + 16896;     // [128][132]
    float* v_s = sm + 33792;     // [128][68] (persists through phase 1)
    // Phase 1 aliases inside [0, 33792)
    float* qph = sm;             // [128][36]
    float* qpl = sm + 4608;
    float* kph = sm + 9216;
    float* kpl = sm + 13824;
    float* psh = sm + 18432;     // [32][68]
    float* psl = sm + 20608;
    __shared__ float Ss_s[32];
    __shared__ float den1[128], den2[128];

    int tid = threadIdx.x, lane = tid & 31, wid = tid >> 5;
    int g = lane >> 2, t = lane & 3;
    int wr = wid >> 3, wc = wid & 7;   // 2 x 8 warps
    int bh = blockIdx.x >> 4, j = blockIdx.x & 15;
    int b = bh >> 3, h = bh & 7;
    size_t rowbase = (size_t)(b * 2048 + j * 128) * 8 + h;

    float CA[4][2][4];   // A: rows wr*64+mt*16, cols wc*16+nt*8
    float CN[4][4];      // NP/AV: rows wr*64+mt*16, cols wc*8
    #pragma unroll
    for (int mt = 0; mt < 4; mt++) {
        #pragma unroll
        for (int nt = 0; nt < 2; nt++)
            #pragma unroll
            for (int i = 0; i < 4; i++) CA[mt][nt][i] = 0.f;
        #pragma unroll
        for (int i = 0; i < 4; i++) CN[mt][i] = 0.f;
    }
    float denq = 0.f;

    #pragma unroll 1
    for (int kc = 0; kc < 8; kc++) {
        __syncthreads();
        for (int idx = tid; idx < 1024; idx += 512) {   // qp chunk: split
            int r = idx >> 3, k4 = idx & 7;
            float4 x = *(const float4*)&g_qp[(rowbase + (size_t)r * 8) * 256 + kc*32 + k4*4];
            float2 sx = tfsplit(x.x), sy = tfsplit(x.y);
            float2 sz = tfsplit(x.z), sw = tfsplit(x.w);
            *(float4*)&qph[r*36 + k4*4] = make_float4(sx.x, sy.x, sz.x, sw.x);
            *(float4*)&qpl[r*36 + k4*4] = make_float4(sx.y, sy.y, sz.y, sw.y);
        }
        for (int idx = tid; idx < 1024; idx += 512) {   // kp chunk: split
            int r = idx >> 3, k4 = idx & 7;
            float4 x = *(const float4*)&g_kp[(rowbase + (size_t)r * 8) * 256 + kc*32 + k4*4];
            float2 sx = tfsplit(x.x), sy = tfsplit(x.y);
            float2 sz = tfsplit(x.z), sw = tfsplit(x.w);
            *(float4*)&kph[r*36 + k4*4] = make_float4(sx.x, sy.x, sz.x, sw.x);
            *(float4*)&kpl[r*36 + k4*4] = make_float4(sx.y, sy.y, sz.y, sw.y);
        }
        for (int idx = tid; idx < 512; idx += 512) {    // Ps chunk: split
            int kk = idx >> 4, d4 = idx & 15;
            float4 x = *(const float4*)&g_kv[(size_t)blockIdx.x * 16384 + (kc*32 + kk)*64 + d4*4];
            float2 sx = tfsplit(x.x), sy = tfsplit(x.y);
            float2 sz = tfsplit(x.z), sw = tfsplit(x.w);
            *(float4*)&psh[kk*68 + d4*4] = make_float4(sx.x, sy.x, sz.x, sw.x);
            *(float4*)&psl[kk*68 + d4*4] = make_float4(sx.y, sy.y, sz.y, sw.y);
        }
        if (tid < 32) Ss_s[tid] = g_s[blockIdx.x * 256 + kc*32 + tid];
        if (kc == 0) {
            for (int idx = tid; idx < 2048; idx += 512) {   // V fp32
                int u = idx >> 4, d4 = idx & 15;
                *(float4*)&v_s[u*68 + d4*4] =
                    *(const float4*)&v[(rowbase + (size_t)u * 8) * 64 + d4*4];
            }
        }
        __syncthreads();

        #pragma unroll
        for (int k0 = 0; k0 < 32; k0 += 8) {
            FA a[4]; FB bA[2], bP;
            #pragma unroll
            for (int mt = 0; mt < 4; mt++) ldaHL(a[mt], qph, qpl, 36, wr*64 + mt*16, k0, g, t);
            #pragma unroll
            for (int nt = 0; nt < 2; nt++) ldbHL_nk(bA[nt], kph, kpl, 36, wc*16 + nt*8, k0, g, t);
            ldbHL_kn(bP, psh, psl, 68, k0, wc*8, g, t);
            #pragma unroll
            for (int mt = 0; mt < 4; mt++) {
                #pragma unroll
                for (int nt = 0; nt < 2; nt++)
                    if (wc*16 + nt*8 <= wr*64 + mt*16 + 15)   // skip fully-masked tiles
                        mma3(CA[mt][nt], a[mt], bA[nt]);
                mma3(CN[mt], a[mt], bP);
            }
        }
        if (tid < 128) {
            #pragma unroll
            for (int kk = 0; kk < 32; kk++)
                denq += (qph[tid*36 + kk] + qpl[tid*36 + kk]) * Ss_s[kk];
        }
    }
    __syncthreads();   // phase-1 smem dead; alias Ah/Al

    #pragma unroll
    for (int mt = 0; mt < 4; mt++)
        #pragma unroll
        for (int nt = 0; nt < 2; nt++) {
            int r = wr*64 + mt*16 + g, c = wc*16 + nt*8 + 2*t;
            float a0 = (c   <= r)   ? CA[mt][nt][0] : 0.f;
            float a1 = (c+1 <= r)   ? CA[mt][nt][1] : 0.f;
            float a2 = (c   <= r+8) ? CA[mt][nt][2] : 0.f;
            float a3 = (c+1 <= r+8) ? CA[mt][nt][3] : 0.f;
            float2 s0 = tfsplit(a0), s1 = tfsplit(a1), s2 = tfsplit(a2), s3 = tfsplit(a3);
            *(float2*)&Ah[r*132 + c]     = make_float2(s0.x, s1.x);
            *(float2*)&Al[r*132 + c]     = make_float2(s0.y, s1.y);
            *(float2*)&Ah[(r+8)*132 + c] = make_float2(s2.x, s3.x);
            *(float2*)&Al[(r+8)*132 + c] = make_float2(s2.y, s3.y);
        }
    if (tid < 128) den1[tid] = denq;
    __syncthreads();

    if (tid < 128) {
        float rs = 0.f;
        #pragma unroll
        for (int u = 0; u < 128; u++) rs += Ah[tid*132 + u] + Al[tid*132 + u];
        den2[tid] = rs;
    }

    int kmax = wr*64 + 64;   // rows in this warp-row need u <= wr*64+63
    #pragma unroll 1
    for (int k0 = 0; k0 < kmax; k0 += 8) {
        FA a[4]; FB bV;
        #pragma unroll
        for (int mt = 0; mt < 4; mt++) ldaHL(a[mt], Ah, Al, 132, wr*64 + mt*16, k0, g, t);
        ldbF_kn(bV, v_s, 68, k0, wc*8, g, t);
        #pragma unroll
        for (int mt = 0; mt < 4; mt++)
            if (k0 <= wr*64 + mt*16 + 15)
                mma3(CN[mt], a[mt], bV);
    }
    __syncthreads();

    #pragma unroll
    for (int mt = 0; mt < 4; mt++) {
        int r = wr*64 + mt*16 + g, c = wc*8 + 2*t;
        float den = den1[r] + den2[r];
        den += (fabsf(den) <= 1e-6f) ? 2e-6f : 0.f;
        float inv = 1.f / den;
        *(float2*)&out[(rowbase + (size_t)r * 8) * 64 + c] =
            make_float2(CN[mt][0] * inv, CN[mt][1] * inv);
        float den8 = den1[r+8] + den2[r+8];
        den8 += (fabsf(den8) <= 1e-6f) ? 2e-6f : 0.f;
        float inv8 = 1.f / den8;
        *(float2*)&out[(rowbase + (size_t)(r+8) * 8) * 64 + c] =
            make_float2(CN[mt][2] * inv8, CN[mt][3] * inv8);
    }
}

extern "C" void kernel_launch(void* const* d_in, const int* in_sizes, int n_in,
                              void* d_out, int out_size) {
    const float* q    = (const float*)d_in[0];
    const float* k    = (const float*)d_in[1];
    const float* v    = (const float*)d_in[2];
    const float* proj = (const float*)d_in[3];
    float* out = (float*)d_out;
    (void)in_sizes; (void)n_in; (void)out_size;

    const int SMF = 104448;   // k_feat:  26112 floats
    const int SMK = 83968;    // k_kvblk: 20992 floats
    const int SMA = 169984;   // k_attn:  42496 floats
    cudaFuncSetAttribute(k_feat,  cudaFuncAttributeMaxDynamicSharedMemorySize, SMF);
    cudaFuncSetAttribute(k_kvblk, cudaFuncAttributeMaxDynamicSharedMemorySize, SMK);
    cudaFuncSetAttribute(k_attn,  cudaFuncAttributeMaxDynamicSharedMemorySize, SMA);

    k_init<<<1, 32>>>();
    k_feat<<<1024, 512, SMF>>>(q, proj, 1);
    k_feat<<<1024, 512, SMF>>>(k, proj, 0);
    k_kvblk<<<512, 512, SMK>>>(v);
    k_scan<<<128, 256>>>();
    k_attn<<<512, 512, SMA>>>(v, out);
}